// round 16
// baseline (speedup 1.0000x reference)
#include <cuda_runtime.h>
#include <cuda_fp16.h>
#include <cstdint>

#define Ndim  2048
#define NN    (Ndim * Ndim)
#define NFLAT (Ndim * (Ndim - 1) / 2)
#define BATCHN 8192
#define NT128 (Ndim / 128)            // 16 tiles per dim

// Taylor coefficients 1/i!
#define C0 1.0f
#define C1 1.0f
#define C2 0.5f
#define C3 1.6666666666666666e-1f
#define C4 4.1666666666666664e-2f
#define C5 8.3333333333333332e-3f
#define C6 1.3888888888888889e-3f
#define C7 1.9841269841269841e-4f
#define C8 2.4801587301587302e-5f
#define C9 2.7557319223985893e-6f

// ---------------- scratch (__device__ globals; allocation-free rule) -------
__device__ float  g_S [NN];
__device__ float  g_S2[NN];
__device__ float  g_Wf[NN];
__device__ __half g_Sh  [NN], g_Snh[NN];   // fp16 S and -S
__device__ __half g_S2h [NN];
__device__ __half g_Wh  [NN];
__device__ __half g_R1th[NN];
__device__ __half g_R2th[NN];
__device__ __half g_Qth [NN];

// ---------------------- PTX helpers (base-target legal only) ---------------
__device__ __forceinline__ uint32_t smem_to_u32(const void* p) {
    uint32_t a;
    asm("{ .reg .u64 t; cvta.to.shared.u64 t, %1; cvt.u32.u64 %0, t; }"
        : "=r"(a) : "l"(p));
    return a;
}
__device__ __forceinline__ void cp16(uint32_t s, const void* g) {
    asm volatile("cp.async.cg.shared.global [%0], [%1], 16;" :: "r"(s), "l"(g));
}
#define CP_COMMIT() asm volatile("cp.async.commit_group;" ::: "memory")
#define CP_WAIT(n)  asm volatile("cp.async.wait_group %0;" :: "n"(n) : "memory")

__device__ __forceinline__ void ldm_x4(uint32_t* r, uint32_t addr) {
    asm volatile("ldmatrix.sync.aligned.m8n8.x4.shared.b16 {%0,%1,%2,%3}, [%4];"
                 : "=r"(r[0]), "=r"(r[1]), "=r"(r[2]), "=r"(r[3]) : "r"(addr));
}
__device__ __forceinline__ void mma16816h(float* c, const uint32_t* a,
                                          uint32_t b0, uint32_t b1) {
    asm volatile(
        "mma.sync.aligned.m16n8k16.row.col.f32.f16.f16.f32 "
        "{%0,%1,%2,%3}, {%4,%5,%6,%7}, {%8,%9}, {%0,%1,%2,%3};"
        : "+f"(c[0]), "+f"(c[1]), "+f"(c[2]), "+f"(c[3])
        : "r"(a[0]), "r"(a[1]), "r"(a[2]), "r"(a[3]), "r"(b0), "r"(b1));
}
__device__ __forceinline__ void sts128(uint32_t addr, uint32_t r0, uint32_t r1,
                                       uint32_t r2, uint32_t r3) {
    asm volatile("st.shared.v4.u32 [%0], {%1,%2,%3,%4};"
                 :: "r"(addr), "r"(r0), "r"(r1), "r"(r2), "r"(r3) : "memory");
}

// fp16 tile: 128 rows x 64 cols x 2B = 128 B/row (8 x 16B chunks), XOR swizzle
__device__ __forceinline__ uint32_t swz128(int row, int chunk) {
    return (uint32_t)(row * 128 + ((chunk ^ (row & 7)) << 4));
}

// ---------------------- preprocessing kernels ------------------------------
// Build antisymmetric S (fp32) + fp16 of S and -S in one pass.
__global__ void build_S_h(const float* __restrict__ Sf, float* __restrict__ S,
                          __half* __restrict__ Sh, __half* __restrict__ Snh) {
    int idx = blockIdx.x * blockDim.x + threadIdx.x;
    if (idx >= NN) return;
    int r = idx >> 11;
    int c = idx & (Ndim - 1);
    float v = 0.0f;
    if (r < c)      v =  Sf[r * (2 * Ndim - r - 1) / 2 + (c - r - 1)];
    else if (r > c) v = -Sf[c * (2 * Ndim - c - 1) / 2 + (r - c - 1)];
    S[idx] = v;
    __half h = __float2half_rn(v);
    Sh[idx]  = h;
    Snh[idx] = __hneg(h);             // rn is sign-symmetric
}

// R1^T = C6*I - C7*S + C8*S2 - C9*W  -> fp16
__global__ void lincomb_R1t_h(const float* __restrict__ S, const float* __restrict__ S2,
                              const float* __restrict__ W, __half* __restrict__ out) {
    int idx = blockIdx.x * blockDim.x + threadIdx.x;
    if (idx >= NN) return;
    int r = idx >> 11;
    int c = idx & (Ndim - 1);
    float v = -C7 * S[idx] + C8 * S2[idx] - C9 * W[idx];
    if (r == c) v += C6;
    out[idx] = __float2half_rn(v);
}

// Mirror strictly-lower 128-tiles from upper: dst[r,c] = +-src[c,r].
__global__ void mirror_fh(float* __restrict__ F, __half* __restrict__ Hh, int neg) {
    int t = blockIdx.y;
    int i = 1, rem = t;
    while (rem >= i) { rem -= i; i++; }
    int j = rem;                        // dest tile (i, j), i > j
    int sub = blockIdx.x;
    int sr = (sub >> 2) * 32, sc = (sub & 3) * 32;
    __shared__ float s0[32][33];
    int tx = threadIdx.x, ty = threadIdx.y;        // 32 x 8
#pragma unroll
    for (int q = 0; q < 4; q++) {
        int srow = j * 128 + sc + ty + q * 8;
        int scol = i * 128 + sr + tx;
        s0[ty + q * 8][tx] = F[(size_t)srow * Ndim + scol];
    }
    __syncthreads();
#pragma unroll
    for (int q = 0; q < 4; q++) {
        int drow = i * 128 + sr + ty + q * 8;
        int dcol = j * 128 + sc + tx;
        float v = s0[tx][ty + q * 8];
        if (neg) v = -v;
        F [(size_t)drow * Ndim + dcol] = v;
        Hh[(size_t)drow * Ndim + dcol] = __float2half_rn(v);
    }
}

// ---------------------------------------------------------------------------
// fp16 single-product GEMM:  D[M,Nc] = A[M,K] @ (Bt[Nc,K])^T   (fp32 accum)
//   + eI*I + e1*E1 + e2*E2 (fp32, nullable)
//   outputs: Cf (fp32, nullable), Ch (fp16, nullable)
// CTA tile 128x128, BK=64 (128B rows), 3-stage cp.async, 256 thr, warp 64x32.
// Af != nullptr: A operand is fp32 in gmem, converted to fp16 on load (for X).
// tri != 0: blockIdx.x is a linear upper-triangle tile id (j >= i).
// ---------------------------------------------------------------------------
#define H_TILE_B  16384               // 128 rows x 128 B
#define H_STAGE_B (2 * H_TILE_B)      // A + Bt
#define H_SMEM_B  (3 * H_STAGE_B)     // 98304

__global__ __launch_bounds__(256, 2)
void h16_gemm(const __half* __restrict__ A, const float* __restrict__ Af,
              const __half* __restrict__ Bt,
              float* __restrict__ Cf, __half* __restrict__ Ch,
              const float* __restrict__ E1, float e1,
              const float* __restrict__ E2, float e2, float eI,
              int M, int Nc, int K, int tri)
{
    extern __shared__ __align__(128) char sm[];
    const uint32_t smu = smem_to_u32(sm);

    const int tid  = threadIdx.x;
    const int lane = tid & 31;
    const int wid  = tid >> 5;
    const int wrow = wid & 1;
    const int wcol = wid >> 1;
    const int rl   = lane & 7;
    const int gq   = lane >> 3;

    int bx, by;
    if (tri) {
        int t = blockIdx.x, i = 0;
        while (t >= NT128 - i) { t -= NT128 - i; i++; }
        by = i; bx = i + t;           // j >= i
    } else {
        bx = blockIdx.x; by = blockIdx.y;
    }
    const int rowA = by * 128;
    const int rowB = bx * 128;

    const int arow = rl + (gq & 1) * 8 + wrow * 64;   // + mt*16
    const int achk = gq >> 1;                         // + ks*2
    const int brow = rl + (gq >> 1) * 8 + wcol * 32;  // + ng*16
    const int bchk = gq & 1;                          // + ks*2

    // gmem loads: 1024 16B-chunks per tile, 4 per thread per tile
    const int ldrow = tid >> 3;               // base rows 0..31 (4 steps of 32)
    const int ldc   = tid & 7;

    float acc[64];
#pragma unroll
    for (int i = 0; i < 64; i++) acc[i] = 0.0f;

    const int nt = K / 64;

    auto issue = [&](int kt, int stage) {
        const int kc = kt * 64;
        const uint32_t sb = smu + stage * H_STAGE_B;
        if (Af) {
            // A is fp32: LDG + convert + STS (X path)
#pragma unroll
            for (int q = 0; q < 4; q++) {
                const int row = ldrow + q * 32;
                const float* g = Af + (size_t)(rowA + row) * K + kc + ldc * 8;
                float4 v0 = *reinterpret_cast<const float4*>(g);
                float4 v1 = *reinterpret_cast<const float4*>(g + 4);
                __half2 h0 = __floats2half2_rn(v0.x, v0.y);
                __half2 h1 = __floats2half2_rn(v0.z, v0.w);
                __half2 h2 = __floats2half2_rn(v1.x, v1.y);
                __half2 h3 = __floats2half2_rn(v1.z, v1.w);
                sts128(sb + swz128(row, ldc),
                       *reinterpret_cast<uint32_t*>(&h0),
                       *reinterpret_cast<uint32_t*>(&h1),
                       *reinterpret_cast<uint32_t*>(&h2),
                       *reinterpret_cast<uint32_t*>(&h3));
            }
        } else {
#pragma unroll
            for (int q = 0; q < 4; q++) {
                const int row = ldrow + q * 32;
                cp16(sb + swz128(row, ldc),
                     A + (size_t)(rowA + row) * K + kc + ldc * 8);
            }
        }
#pragma unroll
        for (int q = 0; q < 4; q++) {
            const int row = ldrow + q * 32;
            cp16(sb + H_TILE_B + swz128(row, ldc),
                 Bt + (size_t)(rowB + row) * K + kc + ldc * 8);
        }
    };

    issue(0, 0); CP_COMMIT();
    issue(1, 1); CP_COMMIT();

    int stage = 0;
    for (int kt = 0; kt < nt; kt++) {
        CP_WAIT(1);
        __syncthreads();
        if (kt + 2 < nt) issue(kt + 2, (stage + 2) % 3);
        CP_COMMIT();

        const uint32_t sb = smu + stage * H_STAGE_B;
#pragma unroll
        for (int ks = 0; ks < 4; ks++) {
            uint32_t ah[16], bh[8];
#pragma unroll
            for (int mt = 0; mt < 4; mt++)
                ldm_x4(ah + mt * 4, sb + swz128(arow + mt * 16, achk + ks * 2));
#pragma unroll
            for (int ng = 0; ng < 2; ng++)
                ldm_x4(bh + ng * 4, sb + H_TILE_B + swz128(brow + ng * 16, bchk + ks * 2));
#pragma unroll
            for (int mt = 0; mt < 4; mt++)
#pragma unroll
                for (int n8 = 0; n8 < 4; n8++) {
                    const int bi = (n8 >> 1) * 4 + (n8 & 1) * 2;
                    mma16816h(acc + (mt * 4 + n8) * 4, ah + mt * 4, bh[bi], bh[bi + 1]);
                }
        }
        stage = (stage + 1) % 3;
    }

    // ---------------- epilogue --------------------------------------------
    const int rbase = rowA + wrow * 64 + (lane >> 2);
    const int cbase = rowB + wcol * 32 + (lane & 3) * 2;

#pragma unroll
    for (int mt = 0; mt < 4; mt++) {
#pragma unroll
        for (int n8 = 0; n8 < 4; n8++) {
            const float* c = acc + (mt * 4 + n8) * 4;
            const int col = cbase + n8 * 8;
#pragma unroll
            for (int h = 0; h < 2; h++) {
                const int r = rbase + mt * 16 + h * 8;
                float v0 = c[h * 2], v1 = c[h * 2 + 1];
                const size_t off = (size_t)r * Nc + col;
                if (E1) {
                    float2 e = *reinterpret_cast<const float2*>(E1 + off);
                    v0 += e1 * e.x; v1 += e1 * e.y;
                }
                if (E2) {
                    float2 e = *reinterpret_cast<const float2*>(E2 + off);
                    v0 += e2 * e.x; v1 += e2 * e.y;
                }
                if (eI != 0.0f) {
                    if (r == col)     v0 += eI;
                    if (r == col + 1) v1 += eI;
                }
                if (Cf)
                    *reinterpret_cast<float2*>(Cf + off) = make_float2(v0, v1);
                if (Ch) {
                    __half2 hp = __floats2half2_rn(v0, v1);
                    *reinterpret_cast<uint32_t*>(Ch + off) =
                        *reinterpret_cast<uint32_t*>(&hp);
                }
            }
        }
    }
}

// ---------------------------------------------------------------------------
extern "C" void kernel_launch(void* const* d_in, const int* in_sizes, int n_in,
                              void* d_out, int out_size) {
    const float* X;
    const float* Sf;
    if (in_sizes[0] == NFLAT) { Sf = (const float*)d_in[0]; X = (const float*)d_in[1]; }
    else                      { X  = (const float*)d_in[0]; Sf = (const float*)d_in[1]; }
    float* Y = (float*)d_out;

    float *S, *S2, *Wf;
    __half *Sh, *Snh, *S2h, *Wh, *R1th, *R2th, *Qth;
    cudaGetSymbolAddress((void**)&S,    g_S);
    cudaGetSymbolAddress((void**)&S2,   g_S2);
    cudaGetSymbolAddress((void**)&Wf,   g_Wf);
    cudaGetSymbolAddress((void**)&Sh,   g_Sh);
    cudaGetSymbolAddress((void**)&Snh,  g_Snh);
    cudaGetSymbolAddress((void**)&S2h,  g_S2h);
    cudaGetSymbolAddress((void**)&Wh,   g_Wh);
    cudaGetSymbolAddress((void**)&R1th, g_R1th);
    cudaGetSymbolAddress((void**)&R2th, g_R2th);
    cudaGetSymbolAddress((void**)&Qth,  g_Qth);

    cudaFuncSetAttribute(h16_gemm, cudaFuncAttributeMaxDynamicSharedMemorySize, H_SMEM_B);

    build_S_h<<<NN / 256, 256>>>(Sf, S, Sh, Snh);

    const int nTriUp  = NT128 * (NT128 + 1) / 2;    // 136
    const int nTriLow = NT128 * (NT128 - 1) / 2;    // 120
    dim3 gSq(NT128, NT128);
    dim3 gMir(16, nTriLow), bMir(32, 8);

    // S2 = S @ S  (upper tiles; D = S @ (-S)^T). out: fp32 + fp16. symmetric.
    h16_gemm<<<nTriUp, 256, H_SMEM_B>>>(Sh, nullptr, Snh,
                                        S2, S2h,
                                        nullptr, 0.f, nullptr, 0.f, 0.f,
                                        Ndim, Ndim, Ndim, 1);
    mirror_fh<<<gMir, bMir>>>(S2, S2h, 0);

    // W = S2 @ S  (upper tiles). out: fp32 + fp16. antisymmetric.
    h16_gemm<<<nTriUp, 256, H_SMEM_B>>>(S2h, nullptr, Snh,
                                        Wf, Wh,
                                        nullptr, 0.f, nullptr, 0.f, 0.f,
                                        Ndim, Ndim, Ndim, 1);
    mirror_fh<<<gMir, bMir>>>(Wf, Wh, 1);

    // R1^T = C6 I - C7 S + C8 S2 - C9 W
    lincomb_R1t_h<<<NN / 256, 256>>>(S, S2, Wf, R1th);

    // R2^T = R1^T @ (-W) + C3 I - C4 S + C5 S2    (Bt = W, since (-W)^T = W)
    h16_gemm<<<gSq, 256, H_SMEM_B>>>(R1th, nullptr, Wh,
                                     nullptr, R2th,
                                     S, -C4, S2, C5, C3,
                                     Ndim, Ndim, Ndim, 0);
    // Q^T  = R2^T @ (-W) + C0 I - C1 S + C2 S2    -> fp16 directly
    h16_gemm<<<gSq, 256, H_SMEM_B>>>(R2th, nullptr, Wh,
                                     nullptr, Qth,
                                     S, -C1, S2, C2, C0,
                                     Ndim, Ndim, Ndim, 0);
    // Y = X @ Q   (Bt = Q^T row-major = Qth); X is fp32, converted on load.
    dim3 gY(NT128, BATCHN / 128);
    h16_gemm<<<gY, 256, H_SMEM_B>>>(nullptr, X, Qth,
                                    Y, nullptr,
                                    nullptr, 0.f, nullptr, 0.f, 0.f,
                                    BATCHN, Ndim, Ndim, 0);
}

// round 17
// speedup vs baseline: 1.2489x; 1.2489x over previous
#include <cuda_runtime.h>
#include <cuda_fp16.h>
#include <cstdint>

#define Ndim  2048
#define NN    (Ndim * Ndim)
#define NFLAT (Ndim * (Ndim - 1) / 2)
#define BATCHN 8192
#define NT128 (Ndim / 128)            // 16 tiles per dim

// Taylor coefficients 1/i!  (degree-6 evaluation; deg 7-9 truncated, ~1e-4)
#define C0 1.0f
#define C1 1.0f
#define C2 0.5f
#define C3 1.6666666666666666e-1f
#define C4 4.1666666666666664e-2f
#define C5 8.3333333333333332e-3f
#define C6 1.3888888888888889e-3f

// ---------------- scratch (__device__ globals; allocation-free rule) -------
__device__ float  g_S [NN];
__device__ float  g_S2[NN];
__device__ float  g_Wf[NN];
__device__ __half g_Sh  [NN], g_Snh[NN];   // fp16 S and -S
__device__ __half g_S2h [NN];
__device__ __half g_Wh  [NN];
__device__ __half g_Uth [NN];
__device__ __half g_Qth [NN];
__device__ __half g_Xh  [BATCHN * Ndim];

// ---------------------- PTX helpers (base-target legal only) ---------------
__device__ __forceinline__ uint32_t smem_to_u32(const void* p) {
    uint32_t a;
    asm("{ .reg .u64 t; cvta.to.shared.u64 t, %1; cvt.u32.u64 %0, t; }"
        : "=r"(a) : "l"(p));
    return a;
}
__device__ __forceinline__ void cp16(uint32_t s, const void* g) {
    asm volatile("cp.async.cg.shared.global [%0], [%1], 16;" :: "r"(s), "l"(g));
}
#define CP_COMMIT() asm volatile("cp.async.commit_group;" ::: "memory")
#define CP_WAIT(n)  asm volatile("cp.async.wait_group %0;" :: "n"(n) : "memory")

__device__ __forceinline__ void ldm_x4(uint32_t* r, uint32_t addr) {
    asm volatile("ldmatrix.sync.aligned.m8n8.x4.shared.b16 {%0,%1,%2,%3}, [%4];"
                 : "=r"(r[0]), "=r"(r[1]), "=r"(r[2]), "=r"(r[3]) : "r"(addr));
}
__device__ __forceinline__ void mma16816h(float* c, const uint32_t* a,
                                          uint32_t b0, uint32_t b1) {
    asm volatile(
        "mma.sync.aligned.m16n8k16.row.col.f32.f16.f16.f32 "
        "{%0,%1,%2,%3}, {%4,%5,%6,%7}, {%8,%9}, {%0,%1,%2,%3};"
        : "+f"(c[0]), "+f"(c[1]), "+f"(c[2]), "+f"(c[3])
        : "r"(a[0]), "r"(a[1]), "r"(a[2]), "r"(a[3]), "r"(b0), "r"(b1));
}

// fp16 tile: 128 rows x 32 cols x 2B = 64B/row (4 x 16B chunks), XOR swizzle
__device__ __forceinline__ uint32_t swz64(int row, int chunk) {
    return (uint32_t)(row * 64 + ((chunk ^ ((row >> 1) & 3)) << 4));
}

// ---------------------- preprocessing kernels ------------------------------
// Build antisymmetric S (fp32) + fp16 of S and -S in one pass.
__global__ void build_S_h(const float* __restrict__ Sf, float* __restrict__ S,
                          __half* __restrict__ Sh, __half* __restrict__ Snh) {
    int idx = blockIdx.x * blockDim.x + threadIdx.x;
    if (idx >= NN) return;
    int r = idx >> 11;
    int c = idx & (Ndim - 1);
    float v = 0.0f;
    if (r < c)      v =  Sf[r * (2 * Ndim - r - 1) / 2 + (c - r - 1)];
    else if (r > c) v = -Sf[c * (2 * Ndim - c - 1) / 2 + (r - c - 1)];
    S[idx] = v;
    __half h = __float2half_rn(v);
    Sh[idx]  = h;
    Snh[idx] = __hneg(h);             // rn is sign-symmetric
}

// fp32 -> fp16 bulk convert
__global__ void cvt_h(const float4* __restrict__ src, uint2* __restrict__ dst, int n4) {
    int i = blockIdx.x * blockDim.x + threadIdx.x;
    if (i >= n4) return;
    float4 v = src[i];
    __half2 h01 = __floats2half2_rn(v.x, v.y);
    __half2 h23 = __floats2half2_rn(v.z, v.w);
    dst[i] = make_uint2(*reinterpret_cast<uint32_t*>(&h01),
                        *reinterpret_cast<uint32_t*>(&h23));
}

// U^T = C3*I - C4*S + C5*S2 - C6*W  -> fp16   (U = C3 I + C4 S + C5 S2 + C6 W)
__global__ void lincomb_Ut_h(const float* __restrict__ S, const float* __restrict__ S2,
                             const float* __restrict__ W, __half* __restrict__ out) {
    int idx = blockIdx.x * blockDim.x + threadIdx.x;
    if (idx >= NN) return;
    int r = idx >> 11;
    int c = idx & (Ndim - 1);
    float v = -C4 * S[idx] + C5 * S2[idx] - C6 * W[idx];
    if (r == c) v += C3;
    out[idx] = __float2half_rn(v);
}

// Mirror strictly-lower 128-tiles from upper: dst[r,c] = +-src[c,r].
__global__ void mirror_fh(float* __restrict__ F, __half* __restrict__ Hh, int neg) {
    int t = blockIdx.y;
    int i = 1, rem = t;
    while (rem >= i) { rem -= i; i++; }
    int j = rem;                        // dest tile (i, j), i > j
    int sub = blockIdx.x;
    int sr = (sub >> 2) * 32, sc = (sub & 3) * 32;
    __shared__ float s0[32][33];
    int tx = threadIdx.x, ty = threadIdx.y;        // 32 x 8
#pragma unroll
    for (int q = 0; q < 4; q++) {
        int srow = j * 128 + sc + ty + q * 8;
        int scol = i * 128 + sr + tx;
        s0[ty + q * 8][tx] = F[(size_t)srow * Ndim + scol];
    }
    __syncthreads();
#pragma unroll
    for (int q = 0; q < 4; q++) {
        int drow = i * 128 + sr + ty + q * 8;
        int dcol = j * 128 + sc + tx;
        float v = s0[tx][ty + q * 8];
        if (neg) v = -v;
        F [(size_t)drow * Ndim + dcol] = v;
        Hh[(size_t)drow * Ndim + dcol] = __float2half_rn(v);
    }
}

// ---------------------------------------------------------------------------
// fp16 single-product GEMM:  D[M,Nc] = A[M,K] @ (Bt[Nc,K])^T   (fp32 accum)
//   + eI*I + e1*E1 + e2*E2 (fp32, nullable)
//   outputs: Cf (fp32, nullable), Ch (fp16, nullable)
// CTA tile 128x128, BK=32, 3-stage cp.async, 256 threads, warp 64x32.
// tri != 0: blockIdx.x is a linear upper-triangle tile id (j >= i).
// (verified R15 configuration)
// ---------------------------------------------------------------------------
#define H_TILE_B  8192                // 128 rows x 64 B
#define H_STAGE_B (2 * H_TILE_B)      // A + Bt
#define H_SMEM_B  (3 * H_STAGE_B)     // 49152

__global__ __launch_bounds__(256, 2)
void h16_gemm(const __half* __restrict__ A, const __half* __restrict__ Bt,
              float* __restrict__ Cf, __half* __restrict__ Ch,
              const float* __restrict__ E1, float e1,
              const float* __restrict__ E2, float e2, float eI,
              int M, int Nc, int K, int tri)
{
    extern __shared__ __align__(128) char sm[];
    const uint32_t smu = smem_to_u32(sm);

    const int tid  = threadIdx.x;
    const int lane = tid & 31;
    const int wid  = tid >> 5;
    const int wrow = wid & 1;
    const int wcol = wid >> 1;
    const int rl   = lane & 7;
    const int gq   = lane >> 3;

    int bx, by;
    if (tri) {
        int t = blockIdx.x, i = 0;
        while (t >= NT128 - i) { t -= NT128 - i; i++; }
        by = i; bx = i + t;           // j >= i
    } else {
        bx = blockIdx.x; by = blockIdx.y;
    }
    const int rowA = by * 128;
    const int rowB = bx * 128;

    const int arow = rl + (gq & 1) * 8 + wrow * 64;   // + mt*16
    const int achk = gq >> 1;                         // + ks*2
    const int brow = rl + (gq >> 1) * 8 + wcol * 32;  // + ng*16
    const int bchk = gq & 1;                          // + ks*2

    // gmem loads: 512 16B-chunks per tile, 2 per thread per tile
    const int ldrow0 = tid >> 2;              // rows 0..63
    const int ldc    = tid & 3;
    const uint32_t so0 = swz64(ldrow0,      ldc);
    const uint32_t so1 = swz64(ldrow0 + 64, ldc);

    float acc[64];
#pragma unroll
    for (int i = 0; i < 64; i++) acc[i] = 0.0f;

    const int nt = K / 32;

    auto issue = [&](int kt, int stage) {
        const int kc = kt * 32;
        const uint32_t sb = smu + stage * H_STAGE_B;
        cp16(sb + so0,            A  + (size_t)(rowA + ldrow0)      * K + kc + ldc * 8);
        cp16(sb + so1,            A  + (size_t)(rowA + ldrow0 + 64) * K + kc + ldc * 8);
        cp16(sb + H_TILE_B + so0, Bt + (size_t)(rowB + ldrow0)      * K + kc + ldc * 8);
        cp16(sb + H_TILE_B + so1, Bt + (size_t)(rowB + ldrow0 + 64) * K + kc + ldc * 8);
    };

    issue(0, 0); CP_COMMIT();
    issue(1, 1); CP_COMMIT();

    int stage = 0;
    for (int kt = 0; kt < nt; kt++) {
        CP_WAIT(1);
        __syncthreads();
        if (kt + 2 < nt) issue(kt + 2, (stage + 2) % 3);
        CP_COMMIT();

        const uint32_t sb = smu + stage * H_STAGE_B;
#pragma unroll
        for (int ks = 0; ks < 2; ks++) {
            uint32_t ah[16], bh[8];
#pragma unroll
            for (int mt = 0; mt < 4; mt++)
                ldm_x4(ah + mt * 4, sb + swz64(arow + mt * 16, achk + ks * 2));
#pragma unroll
            for (int ng = 0; ng < 2; ng++)
                ldm_x4(bh + ng * 4, sb + H_TILE_B + swz64(brow + ng * 16, bchk + ks * 2));
#pragma unroll
            for (int mt = 0; mt < 4; mt++)
#pragma unroll
                for (int n8 = 0; n8 < 4; n8++) {
                    const int bi = (n8 >> 1) * 4 + (n8 & 1) * 2;
                    mma16816h(acc + (mt * 4 + n8) * 4, ah + mt * 4, bh[bi], bh[bi + 1]);
                }
        }
        stage = (stage + 1) % 3;
    }

    // ---------------- epilogue --------------------------------------------
    const int rbase = rowA + wrow * 64 + (lane >> 2);
    const int cbase = rowB + wcol * 32 + (lane & 3) * 2;

#pragma unroll
    for (int mt = 0; mt < 4; mt++) {
#pragma unroll
        for (int n8 = 0; n8 < 4; n8++) {
            const float* c = acc + (mt * 4 + n8) * 4;
            const int col = cbase + n8 * 8;
#pragma unroll
            for (int h = 0; h < 2; h++) {
                const int r = rbase + mt * 16 + h * 8;
                float v0 = c[h * 2], v1 = c[h * 2 + 1];
                const size_t off = (size_t)r * Nc + col;
                if (E1) {
                    float2 e = *reinterpret_cast<const float2*>(E1 + off);
                    v0 += e1 * e.x; v1 += e1 * e.y;
                }
                if (E2) {
                    float2 e = *reinterpret_cast<const float2*>(E2 + off);
                    v0 += e2 * e.x; v1 += e2 * e.y;
                }
                if (eI != 0.0f) {
                    if (r == col)     v0 += eI;
                    if (r == col + 1) v1 += eI;
                }
                if (Cf)
                    *reinterpret_cast<float2*>(Cf + off) = make_float2(v0, v1);
                if (Ch) {
                    __half2 hp = __floats2half2_rn(v0, v1);
                    *reinterpret_cast<uint32_t*>(Ch + off) =
                        *reinterpret_cast<uint32_t*>(&hp);
                }
            }
        }
    }
}

// ---------------------------------------------------------------------------
extern "C" void kernel_launch(void* const* d_in, const int* in_sizes, int n_in,
                              void* d_out, int out_size) {
    const float* X;
    const float* Sf;
    if (in_sizes[0] == NFLAT) { Sf = (const float*)d_in[0]; X = (const float*)d_in[1]; }
    else                      { X  = (const float*)d_in[0]; Sf = (const float*)d_in[1]; }
    float* Y = (float*)d_out;

    float *S, *S2, *Wf;
    __half *Sh, *Snh, *S2h, *Wh, *Uth, *Qth, *Xh;
    cudaGetSymbolAddress((void**)&S,    g_S);
    cudaGetSymbolAddress((void**)&S2,   g_S2);
    cudaGetSymbolAddress((void**)&Wf,   g_Wf);
    cudaGetSymbolAddress((void**)&Sh,   g_Sh);
    cudaGetSymbolAddress((void**)&Snh,  g_Snh);
    cudaGetSymbolAddress((void**)&S2h,  g_S2h);
    cudaGetSymbolAddress((void**)&Wh,   g_Wh);
    cudaGetSymbolAddress((void**)&Uth,  g_Uth);
    cudaGetSymbolAddress((void**)&Qth,  g_Qth);
    cudaGetSymbolAddress((void**)&Xh,   g_Xh);

    cudaFuncSetAttribute(h16_gemm, cudaFuncAttributeMaxDynamicSharedMemorySize, H_SMEM_B);

    build_S_h<<<NN / 256, 256>>>(Sf, S, Sh, Snh);
    cvt_h<<<(BATCHN * Ndim / 4) / 256, 256>>>((const float4*)X, (uint2*)Xh,
                                              BATCHN * Ndim / 4);

    const int nTriUp  = NT128 * (NT128 + 1) / 2;    // 136
    const int nTriLow = NT128 * (NT128 - 1) / 2;    // 120
    dim3 gSq(NT128, NT128);
    dim3 gMir(16, nTriLow), bMir(32, 8);

    // S2 = S @ S  (upper tiles; D = S @ (-S)^T). out: fp32 + fp16. symmetric.
    h16_gemm<<<nTriUp, 256, H_SMEM_B>>>(Sh, Snh,
                                        S2, S2h,
                                        nullptr, 0.f, nullptr, 0.f, 0.f,
                                        Ndim, Ndim, Ndim, 1);
    mirror_fh<<<gMir, bMir>>>(S2, S2h, 0);

    // W = S2 @ S  (upper tiles). out: fp32 + fp16. antisymmetric.
    h16_gemm<<<nTriUp, 256, H_SMEM_B>>>(S2h, Snh,
                                        Wf, Wh,
                                        nullptr, 0.f, nullptr, 0.f, 0.f,
                                        Ndim, Ndim, Ndim, 1);
    mirror_fh<<<gMir, bMir>>>(Wf, Wh, 1);

    // U^T = C3 I - C4 S + C5 S2 - C6 W   (degree 3..6 block, incl. c6*W*W term)
    lincomb_Ut_h<<<NN / 256, 256>>>(S, S2, Wf, Uth);

    // Q^T = U^T @ (-W) + C0 I - C1 S + C2 S2    (Bt = W since (-W)^T = W)
    h16_gemm<<<gSq, 256, H_SMEM_B>>>(Uth, Wh,
                                     nullptr, Qth,
                                     S, -C1, S2, C2, C0,
                                     Ndim, Ndim, Ndim, 0);
    // Y = X @ Q   (Bt = Q^T row-major = Qth), fp16 single product
    dim3 gY(NT128, BATCHN / 128);
    h16_gemm<<<gY, 256, H_SMEM_B>>>(Xh, Qth,
                                    Y, nullptr,
                                    nullptr, 0.f, nullptr, 0.f, 0.f,
                                    BATCHN, Ndim, Ndim, 0);
}